// round 4
// baseline (speedup 1.0000x reference)
#include <cuda_runtime.h>

#define HH 4096
#define WW 1024
#define SS 16
#define NSEG 17
#define NCH 64           // 64-row chunks per column (one warp each)
#define NBH 8            // blockIdx.y extent in k_main (8 warps/block * 8 = 64 chunks)
#define WIN 20.0f
#define FINF 3.0e38f

// ---- scratch (__device__ globals; no allocation allowed) -------------------
__device__ float g_p64[NCH * WW];                 // per-chunk column sums
__device__ float g_hB[NCH * NSEG * WW];           // hard partial: count
__device__ float g_hA[NCH * NSEG * WW];           // hard partial: sum(x-shift)
__device__ float g_hC[NCH * NSEG * WW];           // hard partial: sum((x-shift)^2)
__device__ float g_hS[NCH * NSEG * WW];           // hard partial: shift
__device__ float g_w [NBH * 3 * SS * WW];         // window sums (d, d*x, d*x^2)
__device__ float g_sum, g_cnt;
__device__ unsigned g_ticket;

// ---------------------------------------------------------------------------
// Kernel A: per-64-row-chunk column sums (coalesced, lane = column).
// Also zeroes the scalar accumulators for this replay.
// ---------------------------------------------------------------------------
__global__ void __launch_bounds__(256) k_part(const float* __restrict__ preds) {
    if (blockIdx.x == 0 && blockIdx.y == 0 && threadIdx.x == 0) {
        g_sum = 0.f; g_cnt = 0.f; g_ticket = 0u;
    }
    int v = threadIdx.x >> 5, lane = threadIdx.x & 31;
    int col = blockIdx.x * 32 + lane;
    int gi = blockIdx.y * 8 + v;
    const float* p = preds + (size_t)gi * 64 * WW + col;
    float s = 0.f;
#pragma unroll 8
    for (int r = 0; r < 64; r++) s += p[(size_t)r * WW];
    g_p64[gi * WW + col] = s;
}

// ---------------------------------------------------------------------------
// Kernel B: main sweep. Block (bw,bh): 32 columns x 512 rows; warp = one
// 64-row chunk, lane = column. Running normalized cumsum from precomputed
// chunk prefixes; shifted fp32 hard moments (stored per chunk, no atomics);
// sigmoid-window corrections with one-compare-per-row event tracking.
// ---------------------------------------------------------------------------
__global__ void __launch_bounds__(256) k_main(const float* __restrict__ preds,
                                              const float* __restrict__ snakes) {
    __shared__ float snk[SS][32];
    __shared__ float sw[3][SS][32];

    const int bw = blockIdx.x, bh = blockIdx.y;
    const int tid = threadIdx.x;
    const int v = tid >> 5, lane = tid & 31;
    const int col = bw * 32 + lane;

    for (int e = tid; e < SS * 32; e += 256)
        snk[e >> 5][e & 31] = snakes[(e >> 5) * WW + bw * 32 + (e & 31)];
    for (int e = tid; e < 3 * SS * 32; e += 256)
        ((float*)sw)[e] = 0.f;
    __syncthreads();

    // chunk prefix + column total
    const int gi = bh * 8 + v;
    float base = 0.f, mag = 0.f;
#pragma unroll
    for (int i = 0; i < NCH; i++) {
        float pv = g_p64[i * WW + col];
        base += (i < gi) ? pv : 0.f;
        mag += pv;
    }
    const float inv = 1.0f / mag;

    const int h0 = gi * 64;
    const float* p = preds + (size_t)h0 * WW + col;

    // hard segment index: row h is in segment j iff s_{j-1} <= h < s_j
    int j = 0;
    while (j < SS && snk[j][lane] <= (float)h0) j++;
    float sNext = (j < SS) ? snk[j][lane] : FINF;

    // window state: active boundaries b with |s_b - h| <= WIN form [wLo, wHi)
    int wLo = 0, wHi = 0;
    while (wLo < SS && snk[wLo][lane] < (float)h0 - WIN) wLo++;
    while (wHi < SS && snk[wHi][lane] <= (float)h0 + WIN) wHi++;
    float evtR = (wLo < SS) ? snk[wLo][lane] + WIN : FINF;  // retire when hf >  evtR
    float evtA = (wHi < SS) ? snk[wHi][lane] - WIN : FINF;  // activate when hf >= evtA

    float cum = base;
    float A = 0.f, C = 0.f, B = 0.f, sh = 0.f;
    bool need = true;
    const size_t outBase = (size_t)gi * NSEG * WW + col;

    for (int r = 0; r < 64; r++) {
        const float hf = (float)(h0 + r);
        cum += p[(size_t)r * WW];
        const float x = cum * inv;

        if (hf >= sNext) {                    // crossed boundary: flush partial
            size_t o = outBase + (size_t)j * WW;
            g_hB[o] = B; g_hA[o] = A; g_hC[o] = C; g_hS[o] = sh;
            A = C = B = 0.f; need = true;
            j++;
            while (j < SS && snk[j][lane] <= hf) j++;
            sNext = (j < SS) ? snk[j][lane] : FINF;
        }
        if (need) { sh = x; need = false; }
        float dx = x - sh;
        A += dx; C = fmaf(dx, dx, C); B += 1.f;

        if (hf > evtR || hf >= evtA) {        // window state change (rare)
            while (wLo < SS && snk[wLo][lane] < hf - WIN) wLo++;
            while (wHi < SS && snk[wHi][lane] <= hf + WIN) wHi++;
            evtR = (wLo < SS) ? snk[wLo][lane] + WIN : FINF;
            evtA = (wHi < SS) ? snk[wHi][lane] - WIN : FINF;
        }
        for (int b = wLo; b < wHi; b++) {
            float t = snk[b][lane] - hf;
            float u = __expf(-fabsf(t));
            float sg = u / (1.f + u);
            float dlt = (t > 0.f) ? -sg : sg;  // sigmoid - step, stable both sides
            atomicAdd(&sw[0][b][lane], dlt);
            atomicAdd(&sw[1][b][lane], dlt * x);
            atomicAdd(&sw[2][b][lane], dlt * x * x);
        }
    }
    if (B > 0.f) {                            // final flush
        size_t o = outBase + (size_t)j * WW;
        g_hB[o] = B; g_hA[o] = A; g_hC[o] = C; g_hS[o] = sh;
    }
    __syncthreads();

    for (int e = tid; e < 3 * SS * 32; e += 256) {
        int k = e / (SS * 32), rem = e % (SS * 32), b = rem >> 5, l = rem & 31;
        g_w[((bh * 3 + k) * SS + b) * WW + bw * 32 + l] = sw[k][b][l];
    }
}

// ---------------------------------------------------------------------------
// Kernel C: thread = (segment s, column w). Stable merge of 64 chunk
// partials, apply window corrections, accumulate masked loss, finalize.
// ---------------------------------------------------------------------------
__global__ void __launch_bounds__(256) k_cols(float* __restrict__ out) {
    const int g = blockIdx.x * 256 + threadIdx.x;   // 0..17407
    const int w = g & (WW - 1);
    const int s = g >> 10;

    float mag = 0.f;
#pragma unroll
    for (int i = 0; i < NCH; i++) mag += g_p64[i * WW + w];
    const bool mask = (mag > 1.0f);

    // merge hard partials (Chan): (B, mean, M2)
    float B = 0.f, mean = 0.f, M2 = 0.f;
    for (int gi = 0; gi < NCH; gi++) {
        size_t idx = ((size_t)gi * NSEG + s) * WW + w;
        float Bp = g_hB[idx];
        if (Bp > 0.f) {
            float Ap = g_hA[idx], Cp = g_hC[idx], shp = g_hS[idx];
            float mp  = shp + Ap / Bp;
            float m2p = Cp - Ap * Ap / Bp;
            float Bn = B + Bp;
            float d = mp - mean;
            mean += d * Bp / Bn;
            M2 += m2p + d * d * B * (Bp / Bn);
            B = Bn;
        }
    }

    // window corrections: segment s gets +window(s) - window(s-1)
    float D0 = 0.f, D1 = 0.f, D2 = 0.f;
    if (s < SS) {
#pragma unroll
        for (int bh = 0; bh < NBH; bh++) {
            D0 += g_w[((bh * 3 + 0) * SS + s) * WW + w];
            D1 += g_w[((bh * 3 + 1) * SS + s) * WW + w];
            D2 += g_w[((bh * 3 + 2) * SS + s) * WW + w];
        }
    }
    if (s > 0) {
        int b = s - 1;
#pragma unroll
        for (int bh = 0; bh < NBH; bh++) {
            D0 -= g_w[((bh * 3 + 0) * SS + b) * WW + w];
            D1 -= g_w[((bh * 3 + 1) * SS + b) * WW + w];
            D2 -= g_w[((bh * 3 + 2) * SS + b) * WW + w];
        }
    }
    // recenter corrections about hard mean: y = x - mean
    float d1 = D1 - mean * D0;
    float d2 = D2 - 2.f * mean * D1 + mean * mean * D0;
    float Bt = B + D0;
    float V = 0.f;
    if (Bt > 1e-12f) V = (M2 + d2) - d1 * d1 / Bt;

    float contrib = mask ? V : 0.f;
    float cnt = (s == 0 && mask) ? 1.f : 0.f;

    // block reduction
#pragma unroll
    for (int d = 16; d; d >>= 1) {
        contrib += __shfl_xor_sync(0xffffffffu, contrib, d);
        cnt     += __shfl_xor_sync(0xffffffffu, cnt, d);
    }
    __shared__ float rs[8], rc[8];
    __shared__ bool isLast;
    int lane = threadIdx.x & 31, wid = threadIdx.x >> 5;
    if (lane == 0) { rs[wid] = contrib; rc[wid] = cnt; }
    __syncthreads();
    if (threadIdx.x == 0) {
        float S_ = 0.f, C_ = 0.f;
#pragma unroll
        for (int k = 0; k < 8; k++) { S_ += rs[k]; C_ += rc[k]; }
        atomicAdd(&g_sum, S_);
        atomicAdd(&g_cnt, C_);
        __threadfence();
        unsigned t = atomicAdd(&g_ticket, 1u);
        isLast = (t == gridDim.x - 1);
    }
    __syncthreads();
    if (isLast && threadIdx.x == 0)
        out[0] = g_sum / ((float)(NSEG * HH)) / g_cnt;
}

// ---------------------------------------------------------------------------
extern "C" void kernel_launch(void* const* d_in, const int* in_sizes, int n_in,
                              void* d_out, int out_size) {
    const float* snakes = (const float*)d_in[0];   // [16, 1024]
    const float* preds  = (const float*)d_in[1];   // [4096, 1024]
    (void)in_sizes; (void)n_in; (void)out_size;

    k_part<<<dim3(WW / 32, NBH), 256>>>(preds);
    k_main<<<dim3(WW / 32, NBH), 256>>>(preds, snakes);
    k_cols<<<(NSEG * WW) / 256, 256>>>((float*)d_out);
}

// round 7
// speedup vs baseline: 1.7060x; 1.7060x over previous
#include <cuda_runtime.h>

#define HH 4096
#define WW 1024
#define SS 16
#define NSEG 17
#define NCH 64            // 64-row chunks (hard-moment partial granularity)
#define NR32 128          // 32-row groups (k_part granularity)
#define WIN 20.0f
#define FINF 3.0e38f

// ---- scratch (__device__ globals; no allocation allowed) -------------------
__device__ float g_p32[NR32 * WW];        // per-32-row-group column sums
__device__ float g_cum[HH * WW];          // 16MB normalized cumsum
__device__ float g_hB[NCH * NSEG * WW];   // hard partial: count
__device__ float g_hA[NCH * NSEG * WW];   // hard partial: sum(x-shift)
__device__ float g_hC[NCH * NSEG * WW];   // hard partial: sum((x-shift)^2)
__device__ float g_hS[NCH * NSEG * WW];   // hard partial: shift
__device__ float g_w0[SS * WW], g_w1[SS * WW], g_w2[SS * WW];  // window sums
__device__ float g_sum, g_cnt;
__device__ unsigned g_ticket;

// ---------------------------------------------------------------------------
// Kernel A: 32-row-group column sums. warp = group, lane = column. MLP=32.
// Also resets the scalar accumulators for this replay.
// ---------------------------------------------------------------------------
__global__ void __launch_bounds__(256) k_part(const float* __restrict__ preds) {
    if (blockIdx.x == 0 && blockIdx.y == 0 && threadIdx.x == 0) {
        g_sum = 0.f; g_cnt = 0.f; g_ticket = 0u;
    }
    const int v = threadIdx.x >> 5, lane = threadIdx.x & 31;
    const int col = blockIdx.x * 32 + lane;
    const int gi = blockIdx.y * 8 + v;            // 0..127
    const float* p = preds + (size_t)gi * 32 * WW + col;
    float a0 = 0.f, a1 = 0.f, a2 = 0.f, a3 = 0.f;
#pragma unroll
    for (int r = 0; r < 32; r += 4) {
        a0 += p[(size_t)(r + 0) * WW];
        a1 += p[(size_t)(r + 1) * WW];
        a2 += p[(size_t)(r + 2) * WW];
        a3 += p[(size_t)(r + 3) * WW];
    }
    g_p32[gi * WW + col] = (a0 + a1) + (a2 + a3);
}

// ---------------------------------------------------------------------------
// Kernel B: main sweep. warp = 64-row chunk, lane = column. Batched loads
// (MLP=16), running normalized cumsum, stores x to g_cum, shifted fp32 hard
// moments flushed per segment (plain stores, no atomics). NO sigmoids here.
// ---------------------------------------------------------------------------
__global__ void __launch_bounds__(256) k_main(const float* __restrict__ preds,
                                              const float* __restrict__ snakes) {
    __shared__ float s_p[NR32][32];   // 16KB: group sums for this col-group
    __shared__ float snk[SS][32];

    const int bw = blockIdx.x, bh = blockIdx.y;
    const int tid = threadIdx.x;
    const int v = tid >> 5, lane = tid & 31;
    const int col = bw * 32 + lane;

    for (int e = tid; e < NR32 * 32; e += 256)
        s_p[e >> 5][e & 31] = g_p32[(e >> 5) * WW + bw * 32 + (e & 31)];
    for (int e = tid; e < SS * 32; e += 256)
        snk[e >> 5][e & 31] = snakes[(e >> 5) * WW + bw * 32 + (e & 31)];
    __syncthreads();

    const int gi = bh * 8 + v;        // 64-row chunk id, 0..63
    const int h0 = gi * 64;
    const int gpre = gi * 2;          // 32-row groups before this chunk

    float base = 0.f;
#pragma unroll 8
    for (int i = 0; i < gpre; i++) base += s_p[i][lane];
    float mag = base;
#pragma unroll 8
    for (int i = gpre; i < NR32; i++) mag += s_p[i][lane];
    const float inv = 1.0f / mag;

    const float* p = preds + (size_t)h0 * WW + col;
    float* outc = g_cum + (size_t)h0 * WW + col;

    int j = 0;
    while (j < SS && snk[j][lane] <= (float)h0) j++;
    float sNext = (j < SS) ? snk[j][lane] : FINF;

    float cum = base;
    float A = 0.f, C = 0.f, B = 0.f, sh = 0.f;
    bool need = true;
    const size_t outBase = (size_t)gi * NSEG * WW + col;

#pragma unroll
    for (int b = 0; b < 4; b++) {
        float regs[16];
#pragma unroll
        for (int k = 0; k < 16; k++)                       // independent loads
            regs[k] = p[(size_t)(b * 16 + k) * WW];
#pragma unroll
        for (int k = 0; k < 16; k++) {
            const int r = b * 16 + k;
            cum += regs[k];
            const float x = cum * inv;
            outc[(size_t)r * WW] = x;
            const float hf = (float)(h0 + r);
            if (hf >= sNext) {                             // segment crossed
                size_t o = outBase + (size_t)j * WW;
                g_hB[o] = B; g_hA[o] = A; g_hC[o] = C; g_hS[o] = sh;
                A = C = B = 0.f; need = true;
                j++;
                while (j < SS && snk[j][lane] <= hf) j++;
                sNext = (j < SS) ? snk[j][lane] : FINF;
            }
            if (need) { sh = x; need = false; }
            float dx = x - sh;
            A += dx; C = fmaf(dx, dx, C); B += 1.f;
        }
    }
    if (B > 0.f) {
        size_t o = outBase + (size_t)j * WW;
        g_hB[o] = B; g_hA[o] = A; g_hC[o] = C; g_hS[o] = sh;
    }
}

// ---------------------------------------------------------------------------
// Kernel C: window corrections. warp = (boundary b, column w); <=41 rows.
// delta = sigmoid(s-h) - step(s-h); sums of (d, d*x, d*x^2).
// ---------------------------------------------------------------------------
__global__ void __launch_bounds__(256) k_win(const float* __restrict__ snakes) {
    const int u = blockIdx.x * 8 + (threadIdx.x >> 5);   // 0..16383
    const int lane = threadIdx.x & 31;
    const int b = u >> 10, w = u & (WW - 1);
    const float s = snakes[b * WW + w];
    const int lo = max(0, (int)ceilf(s - WIN));
    const int hi = min(HH, (int)floorf(s + WIN) + 1);
    const float* cw = g_cum + w;
    float d0 = 0.f, d1 = 0.f, d2 = 0.f;
    for (int h = lo + lane; h < hi; h += 32) {
        float t = s - (float)h;
        float e = __expf(-fabsf(t));
        float sg = e / (1.f + e);
        float dlt = (t > 0.f) ? -sg : sg;      // sigmoid - step, stable
        float x = cw[(size_t)h * WW];
        d0 += dlt; d1 += dlt * x; d2 = fmaf(dlt * x, x, d2);
    }
#pragma unroll
    for (int d = 16; d; d >>= 1) {
        d0 += __shfl_xor_sync(0xffffffffu, d0, d);
        d1 += __shfl_xor_sync(0xffffffffu, d1, d);
        d2 += __shfl_xor_sync(0xffffffffu, d2, d);
    }
    if (lane == 0) {
        g_w0[b * WW + w] = d0; g_w1[b * WW + w] = d1; g_w2[b * WW + w] = d2;
    }
}

// ---------------------------------------------------------------------------
// Kernel D: thread = (segment s, column w). Chan-merge 64 chunk partials,
// apply window corrections, masked accumulate, last-block finalize.
// ---------------------------------------------------------------------------
__global__ void __launch_bounds__(256) k_cols(float* __restrict__ out) {
    const int g = blockIdx.x * 256 + threadIdx.x;   // 0..17407
    const int w = g & (WW - 1);
    const int s = g >> 10;

    float mag = 0.f;
#pragma unroll 8
    for (int i = 0; i < NR32; i++) mag += g_p32[i * WW + w];
    const bool mask = (mag > 1.0f);

    float B = 0.f, mean = 0.f, M2 = 0.f;
    for (int gi = 0; gi < NCH; gi++) {
        size_t idx = ((size_t)gi * NSEG + s) * WW + w;
        float Bp = g_hB[idx];
        if (Bp > 0.f) {
            float Ap = g_hA[idx], Cp = g_hC[idx], shp = g_hS[idx];
            float mp  = shp + Ap / Bp;
            float m2p = Cp - Ap * Ap / Bp;
            float Bn = B + Bp;
            float d = mp - mean;
            mean += d * Bp / Bn;
            M2 += m2p + d * d * B * (Bp / Bn);
            B = Bn;
        }
    }

    float D0 = 0.f, D1 = 0.f, D2 = 0.f;
    if (s < SS) { D0 += g_w0[s * WW + w]; D1 += g_w1[s * WW + w]; D2 += g_w2[s * WW + w]; }
    if (s > 0)  { int b = s - 1;
                  D0 -= g_w0[b * WW + w]; D1 -= g_w1[b * WW + w]; D2 -= g_w2[b * WW + w]; }

    float d1 = D1 - mean * D0;
    float d2 = D2 - 2.f * mean * D1 + mean * mean * D0;
    float Bt = B + D0;
    float V = (Bt > 1e-12f) ? (M2 + d2) - d1 * d1 / Bt : 0.f;

    float contrib = mask ? V : 0.f;
    float cnt = (s == 0 && mask) ? 1.f : 0.f;

#pragma unroll
    for (int d = 16; d; d >>= 1) {
        contrib += __shfl_xor_sync(0xffffffffu, contrib, d);
        cnt     += __shfl_xor_sync(0xffffffffu, cnt, d);
    }
    __shared__ float rs[8], rc[8];
    __shared__ bool isLast;
    int lane = threadIdx.x & 31, wid = threadIdx.x >> 5;
    if (lane == 0) { rs[wid] = contrib; rc[wid] = cnt; }
    __syncthreads();
    if (threadIdx.x == 0) {
        float S_ = 0.f, C_ = 0.f;
#pragma unroll
        for (int k = 0; k < 8; k++) { S_ += rs[k]; C_ += rc[k]; }
        atomicAdd(&g_sum, S_);
        atomicAdd(&g_cnt, C_);
        __threadfence();
        unsigned t = atomicAdd(&g_ticket, 1u);
        isLast = (t == gridDim.x - 1);
    }
    __syncthreads();
    if (isLast && threadIdx.x == 0)
        out[0] = g_sum / ((float)(NSEG * HH)) / g_cnt;
}

// ---------------------------------------------------------------------------
extern "C" void kernel_launch(void* const* d_in, const int* in_sizes, int n_in,
                              void* d_out, int out_size) {
    const float* snakes = (const float*)d_in[0];   // [16, 1024]
    const float* preds  = (const float*)d_in[1];   // [4096, 1024]
    (void)in_sizes; (void)n_in; (void)out_size;

    k_part<<<dim3(WW / 32, 16), 256>>>(preds);
    k_main<<<dim3(WW / 32, 8), 256>>>(preds, snakes);
    k_win<<<(SS * WW) / 8, 256>>>(snakes);
    k_cols<<<(NSEG * WW) / 256, 256>>>((float*)d_out);
}

// round 9
// speedup vs baseline: 3.1470x; 1.8446x over previous
#include <cuda_runtime.h>

#define HH 4096
#define WW 1024
#define SS 16
#define NSEG 17
#define NCH 64            // 64-row chunks (hard-moment partial granularity)
#define NR32 128          // 32-row groups (k_part granularity)
#define WIN 20.0f
#define FINF 3.0e38f

// ---- scratch (__device__ globals; no allocation allowed) -------------------
__device__ float g_p32[NR32 * WW];        // per-32-row-group column sums
__device__ float g_mag[WW];               // per-column total mass
__device__ float g_cum[HH * WW];          // 16MB normalized cumsum
// hard partials, layout [s][w][gi] for coalesced k_cols reads
__device__ float g_hB[NSEG * WW * NCH];
__device__ float g_hA[NSEG * WW * NCH];
__device__ float g_hC[NSEG * WW * NCH];
__device__ float g_hS[NSEG * WW * NCH];
__device__ float g_w0[SS * WW], g_w1[SS * WW], g_w2[SS * WW];  // window sums
__device__ float g_sum, g_cnt;
__device__ unsigned g_ticket;

// ---------------------------------------------------------------------------
// Kernel A: 32-row-group column sums. warp = group, lane = column. MLP=32.
// Also resets the scalar accumulators for this replay.
// ---------------------------------------------------------------------------
__global__ void __launch_bounds__(256) k_part(const float* __restrict__ preds) {
    if (blockIdx.x == 0 && blockIdx.y == 0 && threadIdx.x == 0) {
        g_sum = 0.f; g_cnt = 0.f; g_ticket = 0u;
    }
    const int v = threadIdx.x >> 5, lane = threadIdx.x & 31;
    const int col = blockIdx.x * 32 + lane;
    const int gi = blockIdx.y * 8 + v;            // 0..127
    const float* p = preds + (size_t)gi * 32 * WW + col;
    float a0 = 0.f, a1 = 0.f, a2 = 0.f, a3 = 0.f;
#pragma unroll
    for (int r = 0; r < 32; r += 4) {
        a0 += p[(size_t)(r + 0) * WW];
        a1 += p[(size_t)(r + 1) * WW];
        a2 += p[(size_t)(r + 2) * WW];
        a3 += p[(size_t)(r + 3) * WW];
    }
    g_p32[gi * WW + col] = (a0 + a1) + (a2 + a3);
}

// ---------------------------------------------------------------------------
// Kernel B: main sweep. warp = 64-row chunk, lane = column. Batched loads
// (MLP=16), running normalized cumsum, stores x to g_cum, shifted fp32 hard
// moments flushed per segment (plain stores, no atomics). NO sigmoids here.
// ---------------------------------------------------------------------------
__global__ void __launch_bounds__(256) k_main(const float* __restrict__ preds,
                                              const float* __restrict__ snakes) {
    __shared__ float s_p[NR32][32];   // 16KB: group sums for this col-group
    __shared__ float snk[SS][32];

    const int bw = blockIdx.x, bh = blockIdx.y;
    const int tid = threadIdx.x;
    const int v = tid >> 5, lane = tid & 31;
    const int col = bw * 32 + lane;

    for (int e = tid; e < NR32 * 32; e += 256)
        s_p[e >> 5][e & 31] = g_p32[(e >> 5) * WW + bw * 32 + (e & 31)];
    for (int e = tid; e < SS * 32; e += 256)
        snk[e >> 5][e & 31] = snakes[(e >> 5) * WW + bw * 32 + (e & 31)];
    __syncthreads();

    const int gi = bh * 8 + v;        // 64-row chunk id, 0..63
    const int h0 = gi * 64;
    const int gpre = gi * 2;          // 32-row groups before this chunk

    float base = 0.f;
#pragma unroll 8
    for (int i = 0; i < gpre; i++) base += s_p[i][lane];
    float mag = base;
#pragma unroll 8
    for (int i = gpre; i < NR32; i++) mag += s_p[i][lane];
    const float inv = 1.0f / mag;
    if (gi == 0) g_mag[col] = mag;

    const float* p = preds + (size_t)h0 * WW + col;
    float* outc = g_cum + (size_t)h0 * WW + col;

    int j = 0;
    while (j < SS && snk[j][lane] <= (float)h0) j++;
    float sNext = (j < SS) ? snk[j][lane] : FINF;

    float cum = base;
    float A = 0.f, C = 0.f, B = 0.f, sh = 0.f;
    bool need = true;

#pragma unroll
    for (int b = 0; b < 4; b++) {
        float regs[16];
#pragma unroll
        for (int k = 0; k < 16; k++)                       // independent loads
            regs[k] = p[(size_t)(b * 16 + k) * WW];
#pragma unroll
        for (int k = 0; k < 16; k++) {
            const int r = b * 16 + k;
            cum += regs[k];
            const float x = cum * inv;
            outc[(size_t)r * WW] = x;
            const float hf = (float)(h0 + r);
            if (hf >= sNext) {                             // segment crossed
                size_t o = ((size_t)j * WW + col) * NCH + gi;
                g_hB[o] = B; g_hA[o] = A; g_hC[o] = C; g_hS[o] = sh;
                A = C = B = 0.f; need = true;
                j++;
                while (j < SS && snk[j][lane] <= hf) j++;
                sNext = (j < SS) ? snk[j][lane] : FINF;
            }
            if (need) { sh = x; need = false; }
            float dx = x - sh;
            A += dx; C = fmaf(dx, dx, C); B += 1.f;
        }
    }
    if (B > 0.f) {
        size_t o = ((size_t)j * WW + col) * NCH + gi;
        g_hB[o] = B; g_hA[o] = A; g_hC[o] = C; g_hS[o] = sh;
    }
}

// ---------------------------------------------------------------------------
// Kernel C: window corrections. warp = (boundary b, column w); <=41 rows.
// delta = sigmoid(s-h) - step(s-h); sums of (d, d*x, d*x^2).
// ---------------------------------------------------------------------------
__global__ void __launch_bounds__(256) k_win(const float* __restrict__ snakes) {
    const int u = blockIdx.x * 8 + (threadIdx.x >> 5);   // 0..16383
    const int lane = threadIdx.x & 31;
    const int b = u >> 10, w = u & (WW - 1);
    const float s = snakes[b * WW + w];
    const int lo = max(0, (int)ceilf(s - WIN));
    const int hi = min(HH, (int)floorf(s + WIN) + 1);
    const float* cw = g_cum + w;
    float d0 = 0.f, d1 = 0.f, d2 = 0.f;
    for (int h = lo + lane; h < hi; h += 32) {
        float t = s - (float)h;
        float e = __expf(-fabsf(t));
        float sg = e / (1.f + e);
        float dlt = (t > 0.f) ? -sg : sg;      // sigmoid - step, stable
        float x = cw[(size_t)h * WW];
        d0 += dlt; d1 += dlt * x; d2 = fmaf(dlt * x, x, d2);
    }
#pragma unroll
    for (int d = 16; d; d >>= 1) {
        d0 += __shfl_xor_sync(0xffffffffu, d0, d);
        d1 += __shfl_xor_sync(0xffffffffu, d1, d);
        d2 += __shfl_xor_sync(0xffffffffu, d2, d);
    }
    if (lane == 0) {
        g_w0[b * WW + w] = d0; g_w1[b * WW + w] = d1; g_w2[b * WW + w] = d2;
    }
}

// ---------------------------------------------------------------------------
// Kernel D: warp = (segment s, column w). Coalesced load of 64 chunk
// partials (2/lane), common-ref transform (branchless; empty slots are
// all-zero no-ops), shuffle-tree merge, window corrections, finalize.
// Grid MUST supply NSEG*WW warps = 2176 blocks of 8 warps.
// ---------------------------------------------------------------------------
__global__ void __launch_bounds__(256) k_cols(float* __restrict__ out) {
    const int wid = threadIdx.x >> 5, lane = threadIdx.x & 31;
    const int u = blockIdx.x * 8 + wid;       // 0..17407
    const int s = u >> 10;
    const int w = u & (WW - 1);
    const size_t bp = (size_t)(s * WW + w) * NCH;

    float B0 = g_hB[bp + lane],      A0 = g_hA[bp + lane];
    float C0 = g_hC[bp + lane],      S0 = g_hS[bp + lane];
    float B1 = g_hB[bp + lane + 32], A1 = g_hA[bp + lane + 32];
    float C1 = g_hC[bp + lane + 32], S1 = g_hS[bp + lane + 32];

    // common reference = B-weighted mean of shifts
    float bs = B0 + B1;
    float ws = fmaf(B0, S0, B1 * S1);
#pragma unroll
    for (int d = 16; d; d >>= 1) {
        bs += __shfl_xor_sync(0xffffffffu, bs, d);
        ws += __shfl_xor_sync(0xffffffffu, ws, d);
    }
    const float ref = (bs > 0.f) ? ws / bs : 0.f;

    // transform both partials to ref and add (empty slots contribute 0)
    float e0 = S0 - ref, e1 = S1 - ref;
    float a = fmaf(B0, e0, A0) + fmaf(B1, e1, A1);
    float c = (C0 + e0 * fmaf(B0, e0, 2.f * A0))
            + (C1 + e1 * fmaf(B1, e1, 2.f * A1));
#pragma unroll
    for (int d = 16; d; d >>= 1) {
        a += __shfl_xor_sync(0xffffffffu, a, d);
        c += __shfl_xor_sync(0xffffffffu, c, d);
    }

    __shared__ float rs[8], rc[8];
    __shared__ bool isLast;
    if (lane == 0) {
        float B = bs, mean = 0.f, M2 = 0.f;
        if (B > 0.f) { mean = ref + a / B; M2 = c - a * a / B; }

        float D0 = 0.f, D1 = 0.f, D2 = 0.f;
        if (s < SS) { D0 += g_w0[s * WW + w]; D1 += g_w1[s * WW + w]; D2 += g_w2[s * WW + w]; }
        if (s > 0)  { int b = s - 1;
                      D0 -= g_w0[b * WW + w]; D1 -= g_w1[b * WW + w]; D2 -= g_w2[b * WW + w]; }

        float d1c = D1 - mean * D0;
        float d2c = D2 - 2.f * mean * D1 + mean * mean * D0;
        float Bt = B + D0;
        float V = (Bt > 1e-12f) ? (M2 + d2c) - d1c * d1c / Bt : 0.f;

        bool mask = g_mag[w] > 1.0f;
        rs[wid] = mask ? V : 0.f;
        rc[wid] = (s == 0 && mask) ? 1.f : 0.f;
    }
    __syncthreads();
    if (threadIdx.x == 0) {
        float S_ = 0.f, C_ = 0.f;
#pragma unroll
        for (int k = 0; k < 8; k++) { S_ += rs[k]; C_ += rc[k]; }
        atomicAdd(&g_sum, S_);
        atomicAdd(&g_cnt, C_);
        __threadfence();
        unsigned t = atomicAdd(&g_ticket, 1u);
        isLast = (t == gridDim.x - 1);
    }
    __syncthreads();
    if (isLast && threadIdx.x == 0)
        out[0] = g_sum / ((float)(NSEG * HH)) / g_cnt;
}

// ---------------------------------------------------------------------------
extern "C" void kernel_launch(void* const* d_in, const int* in_sizes, int n_in,
                              void* d_out, int out_size) {
    const float* snakes = (const float*)d_in[0];   // [16, 1024]
    const float* preds  = (const float*)d_in[1];   // [4096, 1024]
    (void)in_sizes; (void)n_in; (void)out_size;

    k_part<<<dim3(WW / 32, 16), 256>>>(preds);
    k_main<<<dim3(WW / 32, 8), 256>>>(preds, snakes);
    k_win<<<(SS * WW) / 8, 256>>>(snakes);
    k_cols<<<(NSEG * WW * 32) / 256, 256>>>((float*)d_out);   // 2176 blocks: warp per (s,w)
}